// round 17
// baseline (speedup 1.0000x reference)
#include <cuda_runtime.h>
#include <cstdint>

// Problem constants
#define BSZ     8
#define KDIM    4096
#define NDIM    11008
#define RPW     8                        // rows per warp task
#define SPLITK  4                        // kc groups (CTA-pinned)
#define KCH     (KDIM / SPLITK)          // 1024 floats per CTA K-chunk
#define KSUB    (KCH / 2)                // 512 floats per task
#define KITERS  (KSUB / 128)             // 4 iterations (128 k per iter)
#define NSLICES (SPLITK * 2)             // 8 partial slices
#define WARPS_PER_CTA 16
#define THREADS (WARPS_PER_CTA * 32)     // 512
#define CTAS_PER_KC 37
#define NCTAS   (CTAS_PER_KC * SPLITK)   // 148
#define WARPS_PER_KC (CTAS_PER_KC * WARPS_PER_CTA)   // 592
#define NROWGROUPS (NDIM / RPW)          // 1376
#define NTASKS_KC (NROWGROUPS * 2)       // 2752 tasks per kc
#define SMEM_BYTES (BSZ * KCH * 4)       // 32768 (xT, swizzled)

// Split-K partial sums: [NSLICES][BSZ][NDIM]
__device__ float g_partial[NSLICES * BSZ * NDIM];
// grid-barrier counters (zero at load; restored to 0 every run)
__device__ int g_arrive;
__device__ int g_done;

typedef unsigned long long ull;

// ---- packed f32x2 ops (Blackwell f32x2 pipe) ----
__device__ __forceinline__ void ffma2(ull& d, ull a, ull b) {
    asm("fma.rn.f32x2 %0, %1, %2, %0;" : "+l"(d) : "l"(a), "l"(b));
}
__device__ __forceinline__ ull addf32x2(ull a, ull b) {
    ull r;
    asm("add.rn.f32x2 %0, %1, %2;" : "=l"(r) : "l"(a), "l"(b));
    return r;
}
__device__ __forceinline__ ull pk2same(float w) {
    ull r;
    asm("mov.b64 %0, {%1, %1};" : "=l"(r) : "f"(w));
    return r;
}
__device__ __forceinline__ void unpk2(ull a, float& lo, float& hi) {
    asm("mov.b64 {%0, %1}, %2;" : "=f"(lo), "=f"(hi) : "l"(a));
}
// streaming 128-bit weight load (bypass L1 reuse)
__device__ __forceinline__ float4 ldg_cs_f4(const float* p) {
    float4 v;
    asm("ld.global.cs.v4.f32 {%0, %1, %2, %3}, [%4];"
        : "=f"(v.x), "=f"(v.y), "=f"(v.z), "=f"(v.w) : "l"(p));
    return v;
}
__device__ __forceinline__ uint32_t smem_u32(const void* p) {
    uint32_t a;
    asm("{ .reg .u64 t; cvta.to.shared.u64 t, %1; cvt.u32.u64 %0, t; }"
        : "=r"(a) : "l"(p));
    return a;
}
__device__ __forceinline__ void lds_v2u64(uint32_t addr, ull& a, ull& b) {
    asm volatile("ld.shared.v2.u64 {%0, %1}, [%2];"
                 : "=l"(a), "=l"(b) : "r"(addr));
}
__device__ __forceinline__ int ldg_cg_s32(const int* p) {
    int v;
    asm volatile("ld.global.cg.s32 %0, [%1];" : "=r"(v) : "l"(p));
    return v;
}
__device__ __forceinline__ float4 ldg_cg_f4(const float* p) {
    float4 v;
    asm volatile("ld.global.cg.v4.f32 {%0, %1, %2, %3}, [%4];"
        : "=f"(v.x), "=f"(v.y), "=f"(v.z), "=f"(v.w) : "l"(p));
    return v;
}
// xT swizzled address: element (k_local, b) -> (k*32 + b*4) ^ (((k>>2)&7)<<4)
__device__ __forceinline__ uint32_t xaddr(uint32_t k, uint32_t b4) {
    return ((k << 5) + b4) ^ (((k >> 2) & 7u) << 4);
}

extern __shared__ char xsm[];   // xT[k][b], 16B slots XOR-swizzled

__global__ __launch_bounds__(THREADS, 1)
void asl_gemv_kernel(const float* __restrict__ x,
                     const float* __restrict__ w,
                     float* __restrict__ out) {
    const int tid       = threadIdx.x;
    const int kc        = blockIdx.x & 3;        // fixed K-chunk per CTA
    const int cta_in_kc = blockIdx.x >> 2;       // 0..36
    const int kbase     = kc * KCH;

    // ---- stage this kc's x chunk transposed + swizzled (32 KB) ----
    {
        const float4* x4 = reinterpret_cast<const float4*>(x);
        #pragma unroll 4
        for (int i4 = tid; i4 < BSZ * KCH / 4; i4 += THREADS) {
            const int b  = i4 >> 8;              // / (KCH/4)
            const int o  = i4 & 255;
            const int k0 = o * 4;                // local k of first elem
            float4 xv = x4[b * (KDIM / 4) + (kbase >> 2) + o];
            const uint32_t b4 = (uint32_t)b << 2;
            *reinterpret_cast<float*>(xsm + xaddr(k0 + 0, b4)) = xv.x;
            *reinterpret_cast<float*>(xsm + xaddr(k0 + 1, b4)) = xv.y;
            *reinterpret_cast<float*>(xsm + xaddr(k0 + 2, b4)) = xv.z;
            *reinterpret_cast<float*>(xsm + xaddr(k0 + 3, b4)) = xv.w;
        }
    }
    __syncthreads();

    const int lane = tid & 31;
    const int wid  = tid >> 5;
    const uint32_t xbase = smem_u32(xsm);

    for (int t = cta_in_kc * WARPS_PER_CTA + wid; t < NTASKS_KC;
         t += WARPS_PER_KC) {
        const int rg      = t >> 1;              // row group
        const int sub     = t & 1;               // k half within kc
        const int n0      = rg * RPW;
        const int klocal0 = sub * KSUB;          // x smem k offset

        const float* wrow = w + (size_t)n0 * KDIM + kbase + klocal0;

        // acc[r][p]: f32x2 packs batches (2p, 2p+1)
        ull acc[RPW][4];
        #pragma unroll
        for (int r = 0; r < RPW; r++)
            #pragma unroll
            for (int p = 0; p < 4; p++)
                acc[r][p] = 0ULL;

        #pragma unroll 2
        for (int it = 0; it < KITERS; it++) {
            const int k0 = it * 128 + lane * 4;  // within sub-chunk

            float4 wv[RPW];
            #pragma unroll
            for (int r = 0; r < RPW; r++)
                wv[r] = ldg_cs_f4(wrow + (size_t)r * KDIM + k0);

            const uint32_t klb = (uint32_t)(klocal0 + k0);
            #pragma unroll
            for (int j = 0; j < 4; j++) {
                const uint32_t kl = klb + j;
                const uint32_t c4 = ((kl >> 2) & 7u) << 4;
                ull x0, x1, x2, x3;
                lds_v2u64(xbase + ((kl << 5) ^ c4),          x0, x1);
                lds_v2u64(xbase + (((kl << 5) + 16) ^ c4),   x2, x3);

                #pragma unroll
                for (int r = 0; r < RPW; r++) {
                    const float wj = (j == 0) ? wv[r].x :
                                     (j == 1) ? wv[r].y :
                                     (j == 2) ? wv[r].z : wv[r].w;
                    const ull ws = pk2same(wj);
                    ffma2(acc[r][0], ws, x0);
                    ffma2(acc[r][1], ws, x1);
                    ffma2(acc[r][2], ws, x2);
                    ffma2(acc[r][3], ws, x3);
                }
            }
        }

        // ---- butterfly on 32 packed pairs (each ULL = 2 batches) ----
        // v[i] <-> (r = i & 7, p = i >> 3); after 5 rounds lane l holds v[l].
        ull v[32];
        #pragma unroll
        for (int p = 0; p < 4; p++)
            #pragma unroll
            for (int r = 0; r < RPW; r++)
                v[p * 8 + r] = acc[r][p];

        #pragma unroll
        for (int s = 16; s >= 1; s >>= 1) {
            const bool hi = (lane & s) != 0;
            #pragma unroll
            for (int j = 0; j < s; j++) {
                ull mine  = hi ? v[j + s] : v[j];
                ull sent  = hi ? v[j]     : v[j + s];
                ull other = __shfl_xor_sync(0xFFFFFFFFu, sent, s);
                v[j] = addf32x2(mine, other);
            }
        }

        const int p = lane >> 3, r = lane & 7;
        float f0, f1;
        unpk2(v[0], f0, f1);                     // batches 2p, 2p+1
        const int slice = kc * 2 + sub;
        g_partial[((size_t)slice * BSZ + 2 * p)     * NDIM + n0 + r] = f0;
        g_partial[((size_t)slice * BSZ + 2 * p + 1) * NDIM + n0 + r] = f1;
    }

    // ==== grid barrier: ONE fence + arrive per CTA, then spin ====
    __syncthreads();
    if (tid == 0) {
        __threadfence();
        atomicAdd(&g_arrive, 1);
        while (ldg_cg_s32(&g_arrive) < NCTAS)
            __nanosleep(128);
    }
    __syncthreads();

    // ==== cooperative combine: out = sum over NSLICES partials ====
    {
        const int total4 = BSZ * NDIM / 4;                 // 22016
        const int i = blockIdx.x * THREADS + tid;          // 75776 threads
        if (i < total4) {
            const float* p = g_partial;
            float sx = 0.f, sy = 0.f, sz = 0.f, sw = 0.f;
            #pragma unroll
            for (int m = 0; m < NSLICES; m++) {
                float4 a = ldg_cg_f4(p + (size_t)4 * (i + (size_t)m * total4));
                sx += a.x; sy += a.y; sz += a.z; sw += a.w;
            }
            float4 o; o.x = sx; o.y = sy; o.z = sz; o.w = sw;
            reinterpret_cast<float4*>(out)[i] = o;
        }
    }

    // ==== reset counters for next graph replay (last CTA to finish) ====
    __syncthreads();
    if (tid == 0) {
        const int old = atomicAdd(&g_done, 1);
        if (old == NCTAS - 1) {
            g_arrive = 0;
            g_done   = 0;
        }
    }
}

extern "C" void kernel_launch(void* const* d_in, const int* in_sizes, int n_in,
                              void* d_out, int out_size) {
    const float* x = (const float*)d_in[0];
    const float* w = (const float*)d_in[1];
    if (n_in >= 2 && in_sizes[0] == NDIM * KDIM) {   // defensive order fix
        const float* t = x; x = w; w = t;
    }
    float* out = (float*)d_out;

    cudaFuncSetAttribute(asl_gemv_kernel,
                         cudaFuncAttributeMaxDynamicSharedMemorySize,
                         SMEM_BYTES);

    asl_gemv_kernel<<<NCTAS, THREADS, SMEM_BYTES>>>(x, w, out);
}